// round 4
// baseline (speedup 1.0000x reference)
#include <cuda_runtime.h>
#include <cstdint>

#define BATCH 4
#define NPTS  16384
#define NC    1024
#define KNN_K 32

#define F_INF (__int_as_float(0x7f800000))

// ---------------- device scratch (no allocations allowed) ----------------
__device__ int d_cent_idx[BATCH][NC];     // distinct FPS centroid indices (prefix)
__device__ int d_ndist[BATCH];            // number of distinct centroids
__device__ int d_selected[BATCH][NPTS];   // membership mask (dedup)
__device__ int d_sel_idx[BATCH][NPTS];    // compacted selected point indices
__device__ int d_sel_cnt[BATCH];          // count per batch
__device__ int d_feat[BATCH][1024];       // pooled feature as float bits (atomicMax)

// ---------------- kernel 0: reset scratch ----------------
__global__ void reset_kernel() {
    int i = blockIdx.x * blockDim.x + threadIdx.x;
    int stride = gridDim.x * blockDim.x;
    for (int j = i; j < BATCH * NPTS; j += stride) ((int*)d_selected)[j] = 0;
    if (i < BATCH * 1024) ((int*)d_feat)[i] = 0;
    if (i < BATCH) d_sel_cnt[i] = 0;
}

// ---------------- kernel 1: FPS chain with cycle detection ----------------
// far_{i+1} = argmax_n ||x_n - x[far_i]||^2 ; sequence is purely a function of
// the previous index, so the first repeat makes the rest periodic. We only
// need the distinct prefix (duplicated centroids add no knn-set members).
__global__ __launch_bounds__(512) void fps_kernel(const float* __restrict__ x,
                                                  const int* __restrict__ far_init) {
    const int b = blockIdx.x;
    const float* __restrict__ xb = x + (size_t)b * NPTS * 3;
    __shared__ short seen[NPTS];
    __shared__ float swv[16];
    __shared__ int   swi[16];
    __shared__ int s_far, s_stop;

    int t = threadIdx.x;
    for (int i = t; i < NPTS; i += 512) seen[i] = -1;
    int far = far_init[b];
    if (t == 0) { seen[far] = 0; d_cent_idx[b][0] = far; s_stop = 0; }
    __syncthreads();

    int it;
    for (it = 1; it < NC; ++it) {
        const float cx = xb[3 * far + 0];
        const float cy = xb[3 * far + 1];
        const float cz = xb[3 * far + 2];
        float bv = -1.0f; int bi = 0;
        for (int n = t; n < NPTS; n += 512) {
            float dx = xb[3 * n + 0] - cx;
            float dy = xb[3 * n + 1] - cy;
            float dz = xb[3 * n + 2] - cz;
            // match reference: elementwise mul then left-assoc adds (no fma)
            float d = __fadd_rn(__fadd_rn(__fmul_rn(dx, dx), __fmul_rn(dy, dy)),
                                __fmul_rn(dz, dz));
            if (d > bv) { bv = d; bi = n; }
        }
        #pragma unroll
        for (int o = 16; o > 0; o >>= 1) {
            float ov = __shfl_down_sync(0xffffffffu, bv, o);
            int   oi = __shfl_down_sync(0xffffffffu, bi, o);
            if (ov > bv || (ov == bv && oi < bi)) { bv = ov; bi = oi; }
        }
        if ((t & 31) == 0) { swv[t >> 5] = bv; swi[t >> 5] = bi; }
        __syncthreads();
        if (t == 0) {
            bv = swv[0]; bi = swi[0];
            for (int w = 1; w < 16; w++)
                if (swv[w] > bv || (swv[w] == bv && swi[w] < bi)) { bv = swv[w]; bi = swi[w]; }
            s_far = bi;
            if (seen[bi] >= 0) { s_stop = 1; d_ndist[b] = it; }
            else { seen[bi] = (short)it; d_cent_idx[b][it] = bi; }
        }
        __syncthreads();
        if (s_stop) break;
        far = s_far;
    }
    if (it == NC && t == 0) d_ndist[b] = NC;
}

// ---------------- kernel 2: per-distinct-centroid 32-NN + dedup append ----------------
__global__ __launch_bounds__(256) void knn_kernel(const float* __restrict__ x) {
    const int b = blockIdx.y;
    const int c = blockIdx.x;
    if (c >= d_ndist[b]) return;
    const float* __restrict__ xb = x + (size_t)b * NPTS * 3;
    const int ci = d_cent_idx[b][c];
    const float cx = xb[3 * ci + 0], cy = xb[3 * ci + 1], cz = xb[3 * ci + 2];
    // reference formula: ||c||^2 + ||x||^2 - 2*(c.x)
    const float cn2 = __fadd_rn(__fadd_rn(__fmul_rn(cx, cx), __fmul_rn(cy, cy)),
                                __fmul_rn(cz, cz));
    const int t = threadIdx.x;

    float d2v[64];
    #pragma unroll
    for (int j = 0; j < 64; j++) {
        int n = t + 256 * j;
        float xx = xb[3 * n + 0], yy = xb[3 * n + 1], zz = xb[3 * n + 2];
        float xn2 = __fadd_rn(__fadd_rn(__fmul_rn(xx, xx), __fmul_rn(yy, yy)),
                              __fmul_rn(zz, zz));
        float dot = __fadd_rn(__fadd_rn(__fmul_rn(cx, xx), __fmul_rn(cy, yy)),
                              __fmul_rn(cz, zz));
        d2v[j] = __fsub_rn(__fadd_rn(cn2, xn2), __fmul_rn(2.0f, dot));
    }

    __shared__ float swv[8];
    __shared__ int   swi[8];
    __shared__ int   s_win;

    for (int r = 0; r < KNN_K; r++) {
        float bv = F_INF; int bi = NPTS;
        #pragma unroll
        for (int j = 0; j < 64; j++) {
            int n = t + 256 * j;
            if (d2v[j] < bv) { bv = d2v[j]; bi = n; }
        }
        #pragma unroll
        for (int o = 16; o > 0; o >>= 1) {
            float ov = __shfl_down_sync(0xffffffffu, bv, o);
            int   oi = __shfl_down_sync(0xffffffffu, bi, o);
            if (ov < bv || (ov == bv && oi < bi)) { bv = ov; bi = oi; }
        }
        if ((t & 31) == 0) { swv[t >> 5] = bv; swi[t >> 5] = bi; }
        __syncthreads();
        if (t == 0) {
            bv = swv[0]; bi = swi[0];
            for (int w = 1; w < 8; w++)
                if (swv[w] < bv || (swv[w] == bv && swi[w] < bi)) { bv = swv[w]; bi = swi[w]; }
            s_win = bi;
            int old = atomicExch(&d_selected[b][bi], 1);
            if (!old) {
                int pos = atomicAdd(&d_sel_cnt[b], 1);
                d_sel_idx[b][pos] = bi;
            }
        }
        __syncthreads();
        int win = s_win;
        #pragma unroll
        for (int j = 0; j < 64; j++)
            if (t + 256 * j == win) d2v[j] = F_INF;
        // safe to loop: s_win/swv rewritten only after next round's barrier
    }
}

// ---------------- kernel 3: pointwise MLP (3->64->64->64->128->1024) + maxpool ----------------
#define TILE_P 16
__global__ __launch_bounds__(128) void mlp_kernel(
    const float* __restrict__ x,
    const float* __restrict__ w1, const float* __restrict__ b1,
    const float* __restrict__ w2, const float* __restrict__ b2,
    const float* __restrict__ w3, const float* __restrict__ b3,
    const float* __restrict__ w4, const float* __restrict__ b4,
    const float* __restrict__ w5, const float* __restrict__ b5) {

    const int b    = blockIdx.y;
    const int tile = blockIdx.x;
    const int cnt  = d_sel_cnt[b];
    const int base = tile * TILE_P;
    if (base >= cnt) return;
    const int np = min(TILE_P, cnt - base);

    const float* __restrict__ xb = x + (size_t)b * NPTS * 3;
    const int t = threadIdx.x;

    // padded (65-stride) weights -> conflict-free LDS within warps
    __shared__ float w1s[64 * 4], b1s[64];
    __shared__ float w2s[64 * 65], b2s[64];
    __shared__ float w3s[64 * 65], b3s[64];
    __shared__ float b4s[128];
    __shared__ float h1s[64], h2s[64], h3s[64];
    __shared__ float h4s[TILE_P * 128];

    for (int i = t; i < 64 * 3; i += 128) { w1s[(i / 3) * 4 + (i % 3)] = w1[i]; }
    for (int i = t; i < 64;     i += 128) { b1s[i] = b1[i]; b2s[i] = b2[i]; b3s[i] = b3[i]; }
    for (int i = t; i < 4096;   i += 128) { w2s[(i >> 6) * 65 + (i & 63)] = w2[i]; }
    for (int i = t; i < 4096;   i += 128) { w3s[(i >> 6) * 65 + (i & 63)] = w3[i]; }
    if (t < 128) b4s[t] = b4[t];
    __syncthreads();

    // layers 1-4 for up to 16 points (h4 staged in smem)
    for (int p = 0; p < np; p++) {
        int sel = d_sel_idx[b][base + p];
        float x0 = xb[3 * sel + 0], x1 = xb[3 * sel + 1], x2 = xb[3 * sel + 2];
        if (t < 64) {
            float a = b1s[t];
            a = fmaf(w1s[t * 4 + 0], x0, a);
            a = fmaf(w1s[t * 4 + 1], x1, a);
            a = fmaf(w1s[t * 4 + 2], x2, a);
            h1s[t] = fmaxf(a, 0.f);
        }
        __syncthreads();
        if (t < 64) {
            float a = b2s[t];
            #pragma unroll 8
            for (int i = 0; i < 64; i++) a = fmaf(w2s[t * 65 + i], h1s[i], a);
            h2s[t] = fmaxf(a, 0.f);
        }
        __syncthreads();
        if (t < 64) {
            float a = b3s[t];
            #pragma unroll 8
            for (int i = 0; i < 64; i++) a = fmaf(w3s[t * 65 + i], h2s[i], a);
            h3s[t] = fmaxf(a, 0.f);
        }
        __syncthreads();
        {
            // layer 4 weights read from global (L1-resident, 32KB)
            float a = b4s[t];
            const float* w4r = w4 + t * 64;
            #pragma unroll 8
            for (int i = 0; i < 64; i++) a = fmaf(__ldg(&w4r[i]), h3s[i], a);
            h4s[p * 128 + t] = fmaxf(a, 0.f);
        }
        __syncthreads();
    }

    // layer 5 (128 -> 1024): each thread handles 8 output channels, 16 points
    for (int jj = 0; jj < 8; jj++) {
        const int o = jj * 128 + t;
        float acc[TILE_P];
        #pragma unroll
        for (int p = 0; p < TILE_P; p++) acc[p] = 0.f;
        const float4* __restrict__ wrow = reinterpret_cast<const float4*>(w5 + (size_t)o * 128);
        #pragma unroll 4
        for (int i4 = 0; i4 < 32; i4++) {
            float4 w = wrow[i4];
            #pragma unroll
            for (int p = 0; p < TILE_P; p++) {
                float4 h = *reinterpret_cast<const float4*>(&h4s[p * 128 + i4 * 4]);
                acc[p] = fmaf(w.x, h.x, fmaf(w.y, h.y, fmaf(w.z, h.z, fmaf(w.w, h.w, acc[p]))));
            }
        }
        const float bo = b5[o];
        float vmax = 0.f;  // relu floor; max of relu == relu of max, all >= 0
        #pragma unroll
        for (int p = 0; p < TILE_P; p++)
            if (p < np) vmax = fmaxf(vmax, acc[p] + bo);
        atomicMax(&d_feat[b][o], __float_as_int(vmax));
    }
}

// ---------------- kernel 4: FC head (1024->512->256->3) ----------------
__global__ __launch_bounds__(512) void fc_kernel(
    const float* __restrict__ fw1, const float* __restrict__ fb1,
    const float* __restrict__ fw2, const float* __restrict__ fb2,
    const float* __restrict__ fw3, const float* __restrict__ fb3,
    float* __restrict__ out) {
    __shared__ float gs[1024], h1s[512], h2s[256];
    const int b = blockIdx.x, t = threadIdx.x;
    for (int i = t; i < 1024; i += 512) gs[i] = __int_as_float(d_feat[b][i]);
    __syncthreads();
    {
        float a = fb1[t];
        const float4* __restrict__ w = reinterpret_cast<const float4*>(fw1 + (size_t)t * 1024);
        #pragma unroll 4
        for (int i = 0; i < 256; i++) {
            float4 wv = w[i];
            float4 g4 = *reinterpret_cast<const float4*>(&gs[i * 4]);
            a = fmaf(wv.x, g4.x, fmaf(wv.y, g4.y, fmaf(wv.z, g4.z, fmaf(wv.w, g4.w, a))));
        }
        h1s[t] = fmaxf(a, 0.f);
    }
    __syncthreads();
    if (t < 256) {
        float a = fb2[t];
        const float4* __restrict__ w = reinterpret_cast<const float4*>(fw2 + (size_t)t * 512);
        #pragma unroll 4
        for (int i = 0; i < 128; i++) {
            float4 wv = w[i];
            float4 h = *reinterpret_cast<const float4*>(&h1s[i * 4]);
            a = fmaf(wv.x, h.x, fmaf(wv.y, h.y, fmaf(wv.z, h.z, fmaf(wv.w, h.w, a))));
        }
        h2s[t] = fmaxf(a, 0.f);
    }
    __syncthreads();
    if (t < 3) {
        float a = fb3[t];
        for (int i = 0; i < 256; i++) a = fmaf(fw3[t * 256 + i], h2s[i], a);
        out[b * 3 + t] = a;
    }
}

// ---------------- launch ----------------
extern "C" void kernel_launch(void* const* d_in, const int* in_sizes, int n_in,
                              void* d_out, int out_size) {
    const float* x        = (const float*)d_in[0];
    const int*   far_init = (const int*)  d_in[1];
    const float* w1 = (const float*)d_in[2];  const float* b1 = (const float*)d_in[3];
    const float* w2 = (const float*)d_in[4];  const float* b2 = (const float*)d_in[5];
    const float* w3 = (const float*)d_in[6];  const float* b3 = (const float*)d_in[7];
    const float* w4 = (const float*)d_in[8];  const float* b4 = (const float*)d_in[9];
    const float* w5 = (const float*)d_in[10]; const float* b5 = (const float*)d_in[11];
    const float* fw1 = (const float*)d_in[12]; const float* fb1 = (const float*)d_in[13];
    const float* fw2 = (const float*)d_in[14]; const float* fb2 = (const float*)d_in[15];
    const float* fw3 = (const float*)d_in[16]; const float* fb3 = (const float*)d_in[17];
    float* out = (float*)d_out;

    reset_kernel<<<64, 256>>>();
    fps_kernel<<<BATCH, 512>>>(x, far_init);
    knn_kernel<<<dim3(NC, BATCH), 256>>>(x);
    mlp_kernel<<<dim3((NPTS + TILE_P - 1) / TILE_P, BATCH), 128>>>(
        x, w1, b1, w2, b2, w3, b3, w4, b4, w5, b5);
    fc_kernel<<<BATCH, 512>>>(fw1, fb1, fw2, fb2, fw3, fb3, out);
}

// round 6
// speedup vs baseline: 2.7019x; 2.7019x over previous
#include <cuda_runtime.h>
#include <cstdint>

#define BATCH 4
#define NPTS  16384
#define NC    1024
#define KNN_K 32

#define F_INF (__int_as_float(0x7f800000))

// ---------------- device scratch (no allocations allowed) ----------------
__device__ int   d_cent_idx[BATCH][NC];   // distinct FPS centroid indices (prefix)
__device__ int   d_ndist[BATCH];          // number of distinct centroids
__device__ int   d_feat[BATCH][1024];     // pooled feature as float bits (atomicMax)
__device__ __align__(16) float d_h4[(size_t)BATCH * NC * 128 * 32];  // [b][c][k][p]

// ---------------- kernel 1: FPS chain with cycle detection (+ feat reset) --
// far_{i+1} = argmax_n ||x_n - x[far_i]||^2 ; deterministic map on indices,
// so the first repeated index makes the remainder periodic. Only the distinct
// prefix matters downstream (max-pool is multiplicity-invariant).
__global__ __launch_bounds__(512) void fps_kernel(const float* __restrict__ x,
                                                  const int* __restrict__ far_init) {
    const int b = blockIdx.x;
    const float* __restrict__ xb = x + (size_t)b * NPTS * 3;
    __shared__ short seen[NPTS];
    __shared__ float swv[16];
    __shared__ int   swi[16];
    __shared__ int s_far, s_stop;

    const int t = threadIdx.x;
    for (int i = t; i < 1024; i += 512) d_feat[b][i] = 0;
    for (int i = t; i < NPTS; i += 512) seen[i] = -1;
    int far = far_init[b];
    if (t == 0) { seen[far] = 0; d_cent_idx[b][0] = far; s_stop = 0; }
    __syncthreads();

    int it;
    for (it = 1; it < NC; ++it) {
        const float cx = xb[3 * far + 0];
        const float cy = xb[3 * far + 1];
        const float cz = xb[3 * far + 2];
        float bv = -1.0f; int bi = 0;
        for (int n = t; n < NPTS; n += 512) {
            float dx = xb[3 * n + 0] - cx;
            float dy = xb[3 * n + 1] - cy;
            float dz = xb[3 * n + 2] - cz;
            // match reference rounding exactly (no fma contraction)
            float d = __fadd_rn(__fadd_rn(__fmul_rn(dx, dx), __fmul_rn(dy, dy)),
                                __fmul_rn(dz, dz));
            if (d > bv) { bv = d; bi = n; }
        }
        #pragma unroll
        for (int o = 16; o > 0; o >>= 1) {
            float ov = __shfl_down_sync(0xffffffffu, bv, o);
            int   oi = __shfl_down_sync(0xffffffffu, bi, o);
            if (ov > bv || (ov == bv && oi < bi)) { bv = ov; bi = oi; }
        }
        if ((t & 31) == 0) { swv[t >> 5] = bv; swi[t >> 5] = bi; }
        __syncthreads();
        if (t == 0) {
            bv = swv[0]; bi = swi[0];
            for (int w = 1; w < 16; w++)
                if (swv[w] > bv || (swv[w] == bv && swi[w] < bi)) { bv = swv[w]; bi = swi[w]; }
            s_far = bi;
            if (seen[bi] >= 0) { s_stop = 1; d_ndist[b] = it; }
            else { seen[bi] = (short)it; d_cent_idx[b][it] = bi; }
        }
        __syncthreads();
        if (s_stop) break;
        far = s_far;
    }
    if (it == NC && t == 0) d_ndist[b] = NC;
}

// ---------------- kernel 2: fused KNN + layers 1-4 ----------------
// One block per (centroid-slot, batch). Finds the 32-NN of its centroid, then
// runs the pointwise MLP 3->64->64->64->128 on all 32 points in parallel
// (32 points x 8 channel-lanes = 256 threads), writing h4 to global scratch.
__global__ __launch_bounds__(256) void knn_mlp_kernel(
    const float* __restrict__ x,
    const float* __restrict__ w1, const float* __restrict__ b1,
    const float* __restrict__ w2, const float* __restrict__ b2,
    const float* __restrict__ w3, const float* __restrict__ b3,
    const float* __restrict__ w4, const float* __restrict__ b4) {

    const int b = blockIdx.y;
    const int t = threadIdx.x;
    const float* __restrict__ xb = x + (size_t)b * NPTS * 3;
    const int ndist = d_ndist[b];

    // NOTE: every smem array read through float4* MUST be 16B-aligned;
    // static __shared__ float arrays are only 4B-aligned by default.
    __shared__ __align__(16) float Ha[32][72];  // pad 72 (16B multiple rows)
    __shared__ __align__(16) float Hb[32][72];
    __shared__ __align__(16) float P[32][4];
    __shared__ float swv[8];
    __shared__ int   swi[8];
    __shared__ int   s_wi;
    __shared__ int   s_sel[KNN_K];

    for (int c = blockIdx.x; c < ndist; c += 32) {
        const int ci = d_cent_idx[b][c];
        const float cx = xb[3 * ci + 0], cy = xb[3 * ci + 1], cz = xb[3 * ci + 2];
        // reference formula: ||c||^2 + ||x||^2 - 2*(c.x), exact rounding
        const float cn2 = __fadd_rn(__fadd_rn(__fmul_rn(cx, cx), __fmul_rn(cy, cy)),
                                    __fmul_rn(cz, cz));
        float d2v[64];
        #pragma unroll
        for (int j = 0; j < 64; j++) {
            int n = t + 256 * j;
            float xx = xb[3 * n + 0], yy = xb[3 * n + 1], zz = xb[3 * n + 2];
            float xn2 = __fadd_rn(__fadd_rn(__fmul_rn(xx, xx), __fmul_rn(yy, yy)),
                                  __fmul_rn(zz, zz));
            float dot = __fadd_rn(__fadd_rn(__fmul_rn(cx, xx), __fmul_rn(cy, yy)),
                                  __fmul_rn(cz, zz));
            d2v[j] = __fsub_rn(__fadd_rn(cn2, xn2), __fmul_rn(2.0f, dot));
        }
        // cached per-thread min
        float mv = F_INF; int mi = NPTS;
        #pragma unroll
        for (int j = 0; j < 64; j++)
            if (d2v[j] < mv) { mv = d2v[j]; mi = t + 256 * j; }

        for (int r = 0; r < KNN_K; r++) {
            float bv = mv; int bi = mi;
            #pragma unroll
            for (int o = 16; o > 0; o >>= 1) {
                float ov = __shfl_down_sync(0xffffffffu, bv, o);
                int   oi = __shfl_down_sync(0xffffffffu, bi, o);
                if (ov < bv || (ov == bv && oi < bi)) { bv = ov; bi = oi; }
            }
            if ((t & 31) == 0) { swv[t >> 5] = bv; swi[t >> 5] = bi; }
            __syncthreads();
            if (t < 32) {
                float v = (t < 8) ? swv[t] : F_INF;
                int  ii = (t < 8) ? swi[t] : NPTS;
                #pragma unroll
                for (int o = 4; o > 0; o >>= 1) {
                    float ov = __shfl_down_sync(0xffffffffu, v, o);
                    int   oi = __shfl_down_sync(0xffffffffu, ii, o);
                    if (ov < v || (ov == v && oi < ii)) { v = ov; ii = oi; }
                }
                if (t == 0) { s_wi = ii; s_sel[r] = ii; }
            }
            __syncthreads();
            const int wi = s_wi;
            if ((wi & 255) == t) {     // owner invalidates & refreshes its min
                d2v[wi >> 8] = F_INF;
                mv = F_INF; mi = NPTS;
                #pragma unroll
                for (int j = 0; j < 64; j++)
                    if (d2v[j] < mv) { mv = d2v[j]; mi = t + 256 * j; }
            }
            __syncthreads();
        }

        // gather selected point coordinates
        if (t < 32) {
            int si = s_sel[t];
            P[t][0] = xb[3 * si + 0];
            P[t][1] = xb[3 * si + 1];
            P[t][2] = xb[3 * si + 2];
        }
        __syncthreads();

        const int p  = t >> 3;   // point 0..31
        const int cb = t & 7;    // channel lane 0..7
        const float px = P[p][0], py = P[p][1], pz = P[p][2];

        // layer 1: 3 -> 64 (8 channels per thread)
        #pragma unroll
        for (int j = 0; j < 8; j++) {
            int ch = cb + 8 * j;
            float a = __ldg(&b1[ch]);
            a = fmaf(__ldg(&w1[ch * 3 + 0]), px, a);
            a = fmaf(__ldg(&w1[ch * 3 + 1]), py, a);
            a = fmaf(__ldg(&w1[ch * 3 + 2]), pz, a);
            Ha[p][ch] = fmaxf(a, 0.f);
        }
        __syncthreads();

        // layer 2: 64 -> 64  (Ha -> Hb)
        {
            float acc[8];
            #pragma unroll
            for (int j = 0; j < 8; j++) acc[j] = __ldg(&b2[cb + 8 * j]);
            #pragma unroll 4
            for (int i4 = 0; i4 < 16; i4++) {
                float4 h = *reinterpret_cast<const float4*>(&Ha[p][i4 * 4]);
                #pragma unroll
                for (int j = 0; j < 8; j++) {
                    float4 w = __ldg(reinterpret_cast<const float4*>(w2 + (cb + 8 * j) * 64) + i4);
                    acc[j] = fmaf(w.x, h.x, fmaf(w.y, h.y, fmaf(w.z, h.z, fmaf(w.w, h.w, acc[j]))));
                }
            }
            #pragma unroll
            for (int j = 0; j < 8; j++) Hb[p][cb + 8 * j] = fmaxf(acc[j], 0.f);
        }
        __syncthreads();

        // layer 3: 64 -> 64  (Hb -> Ha)
        {
            float acc[8];
            #pragma unroll
            for (int j = 0; j < 8; j++) acc[j] = __ldg(&b3[cb + 8 * j]);
            #pragma unroll 4
            for (int i4 = 0; i4 < 16; i4++) {
                float4 h = *reinterpret_cast<const float4*>(&Hb[p][i4 * 4]);
                #pragma unroll
                for (int j = 0; j < 8; j++) {
                    float4 w = __ldg(reinterpret_cast<const float4*>(w3 + (cb + 8 * j) * 64) + i4);
                    acc[j] = fmaf(w.x, h.x, fmaf(w.y, h.y, fmaf(w.z, h.z, fmaf(w.w, h.w, acc[j]))));
                }
            }
            #pragma unroll
            for (int j = 0; j < 8; j++) Ha[p][cb + 8 * j] = fmaxf(acc[j], 0.f);
        }
        __syncthreads();

        // layer 4: 64 -> 128  (Ha -> global d_h4[b][c][k][p]), 16 channels/thread
        {
            float acc[16];
            #pragma unroll
            for (int j = 0; j < 16; j++) acc[j] = __ldg(&b4[cb + 8 * j]);
            #pragma unroll 4
            for (int i4 = 0; i4 < 16; i4++) {
                float4 h = *reinterpret_cast<const float4*>(&Ha[p][i4 * 4]);
                #pragma unroll
                for (int j = 0; j < 16; j++) {
                    float4 w = __ldg(reinterpret_cast<const float4*>(w4 + (cb + 8 * j) * 64) + i4);
                    acc[j] = fmaf(w.x, h.x, fmaf(w.y, h.y, fmaf(w.z, h.z, fmaf(w.w, h.w, acc[j]))));
                }
            }
            float* dst = d_h4 + ((size_t)(b * NC + c)) * 4096;
            #pragma unroll
            for (int j = 0; j < 16; j++) {
                int ch = cb + 8 * j;
                dst[ch * 32 + p] = fmaxf(acc[j], 0.f);
            }
        }
        __syncthreads();  // smem reuse across centroid iterations
    }
}

// ---------------- kernel 3: layer 5 (128 -> 1024) + global max pool ----------
// grid = (8 channel-tiles, 32 centroid-slots, BATCH); 128 threads; thread t
// owns output o = bx*128+t, computes it for all 32 points of each centroid,
// keeps a running max (relu floor 0), one atomicMax at the end.
__global__ __launch_bounds__(128) void pool_kernel(const float* __restrict__ w5,
                                                   const float* __restrict__ b5) {
    const int b = blockIdx.z;
    const int t = threadIdx.x;
    const int o = blockIdx.x * 128 + t;
    const int ndist = d_ndist[b];
    __shared__ __align__(16) float h4s[128 * 32];

    const float* __restrict__ wrow = w5 + (size_t)o * 128;
    const float bo = __ldg(&b5[o]);
    float vmax = 0.f;   // relu floor; all pooled values are >= 0

    for (int c = blockIdx.y; c < ndist; c += 32) {
        __syncthreads();
        const float* __restrict__ src = d_h4 + ((size_t)(b * NC + c)) * 4096;
        for (int i = t * 4; i < 4096; i += 128 * 4)
            *reinterpret_cast<float4*>(&h4s[i]) = *reinterpret_cast<const float4*>(&src[i]);
        __syncthreads();

        float acc[32];
        #pragma unroll
        for (int p = 0; p < 32; p++) acc[p] = 0.f;

        #pragma unroll 4
        for (int k4 = 0; k4 < 32; k4++) {
            float4 wv = __ldg(reinterpret_cast<const float4*>(wrow) + k4);
            const float* hk = &h4s[(k4 * 4) * 32];
            #pragma unroll
            for (int kk = 0; kk < 4; kk++) {
                float wk = (&wv.x)[kk];
                const float4* hp = reinterpret_cast<const float4*>(hk + kk * 32);
                #pragma unroll
                for (int p4 = 0; p4 < 8; p4++) {
                    float4 h = hp[p4];   // broadcast across all lanes
                    acc[p4 * 4 + 0] = fmaf(wk, h.x, acc[p4 * 4 + 0]);
                    acc[p4 * 4 + 1] = fmaf(wk, h.y, acc[p4 * 4 + 1]);
                    acc[p4 * 4 + 2] = fmaf(wk, h.z, acc[p4 * 4 + 2]);
                    acc[p4 * 4 + 3] = fmaf(wk, h.w, acc[p4 * 4 + 3]);
                }
            }
        }
        #pragma unroll
        for (int p = 0; p < 32; p++) vmax = fmaxf(vmax, acc[p] + bo);
    }
    // vmax==0 when no centroids processed -> no-op vs init 0
    atomicMax(&d_feat[b][o], __float_as_int(vmax));
}

// ---------------- kernel 4: FC head (1024->512->256->3) ----------------
__global__ __launch_bounds__(512) void fc_kernel(
    const float* __restrict__ fw1, const float* __restrict__ fb1,
    const float* __restrict__ fw2, const float* __restrict__ fb2,
    const float* __restrict__ fw3, const float* __restrict__ fb3,
    float* __restrict__ out) {
    __shared__ __align__(16) float gs[1024];
    __shared__ __align__(16) float h1s[512];
    __shared__ __align__(16) float h2s[256];
    const int b = blockIdx.x, t = threadIdx.x;
    for (int i = t; i < 1024; i += 512) gs[i] = __int_as_float(d_feat[b][i]);
    __syncthreads();
    {
        float a0 = 0.f, a1 = 0.f, a2 = 0.f, a3 = 0.f;
        const float4* __restrict__ w = reinterpret_cast<const float4*>(fw1 + (size_t)t * 1024);
        #pragma unroll 4
        for (int i = 0; i < 256; i += 4) {
            float4 w0 = w[i], g0 = *reinterpret_cast<const float4*>(&gs[4 * i]);
            float4 wA = w[i + 1], gA = *reinterpret_cast<const float4*>(&gs[4 * i + 4]);
            float4 wB = w[i + 2], gB = *reinterpret_cast<const float4*>(&gs[4 * i + 8]);
            float4 wC = w[i + 3], gC = *reinterpret_cast<const float4*>(&gs[4 * i + 12]);
            a0 = fmaf(w0.x, g0.x, fmaf(w0.y, g0.y, fmaf(w0.z, g0.z, fmaf(w0.w, g0.w, a0))));
            a1 = fmaf(wA.x, gA.x, fmaf(wA.y, gA.y, fmaf(wA.z, gA.z, fmaf(wA.w, gA.w, a1))));
            a2 = fmaf(wB.x, gB.x, fmaf(wB.y, gB.y, fmaf(wB.z, gB.z, fmaf(wB.w, gB.w, a2))));
            a3 = fmaf(wC.x, gC.x, fmaf(wC.y, gC.y, fmaf(wC.z, gC.z, fmaf(wC.w, gC.w, a3))));
        }
        h1s[t] = fmaxf(((a0 + a1) + (a2 + a3)) + fb1[t], 0.f);
    }
    __syncthreads();
    if (t < 256) {
        float a0 = 0.f, a1 = 0.f;
        const float4* __restrict__ w = reinterpret_cast<const float4*>(fw2 + (size_t)t * 512);
        #pragma unroll 4
        for (int i = 0; i < 128; i += 2) {
            float4 w0 = w[i], h0 = *reinterpret_cast<const float4*>(&h1s[4 * i]);
            float4 wA = w[i + 1], hA = *reinterpret_cast<const float4*>(&h1s[4 * i + 4]);
            a0 = fmaf(w0.x, h0.x, fmaf(w0.y, h0.y, fmaf(w0.z, h0.z, fmaf(w0.w, h0.w, a0))));
            a1 = fmaf(wA.x, hA.x, fmaf(wA.y, hA.y, fmaf(wA.z, hA.z, fmaf(wA.w, hA.w, a1))));
        }
        h2s[t] = fmaxf((a0 + a1) + fb2[t], 0.f);
    }
    __syncthreads();
    if (t < 3) {
        float a = fb3[t];
        for (int i = 0; i < 256; i++) a = fmaf(fw3[t * 256 + i], h2s[i], a);
        out[b * 3 + t] = a;
    }
}

// ---------------- launch ----------------
extern "C" void kernel_launch(void* const* d_in, const int* in_sizes, int n_in,
                              void* d_out, int out_size) {
    const float* x        = (const float*)d_in[0];
    const int*   far_init = (const int*)  d_in[1];
    const float* w1 = (const float*)d_in[2];  const float* b1 = (const float*)d_in[3];
    const float* w2 = (const float*)d_in[4];  const float* b2 = (const float*)d_in[5];
    const float* w3 = (const float*)d_in[6];  const float* b3 = (const float*)d_in[7];
    const float* w4 = (const float*)d_in[8];  const float* b4 = (const float*)d_in[9];
    const float* w5 = (const float*)d_in[10]; const float* b5 = (const float*)d_in[11];
    const float* fw1 = (const float*)d_in[12]; const float* fb1 = (const float*)d_in[13];
    const float* fw2 = (const float*)d_in[14]; const float* fb2 = (const float*)d_in[15];
    const float* fw3 = (const float*)d_in[16]; const float* fb3 = (const float*)d_in[17];
    float* out = (float*)d_out;

    fps_kernel<<<BATCH, 512>>>(x, far_init);
    knn_mlp_kernel<<<dim3(32, BATCH), 256>>>(x, w1, b1, w2, b2, w3, b3, w4, b4);
    pool_kernel<<<dim3(8, 32, BATCH), 128>>>(w5, b5);
    fc_kernel<<<BATCH, 512>>>(fw1, fb1, fw2, fb2, fw3, fb3, out);
}